// round 7
// baseline (speedup 1.0000x reference)
#include <cuda_runtime.h>

// Model_68616397521448 — fuzzy-rule evidential reasoning, round 7.
// Converged config = empirical best (R4: 512 thr, grid=148, rows interleaved)
// plus the two zero-cost chain cuts validated since:
//  - Sx butterfly reduce hoisted above __syncthreads (overlaps preamble)
//  - d prefetched via __ldg at kernel top
//  - exponent in log2 domain (ex2.approx, no per-exp FMUL)
//  - division-free ER combine in packed f32x2 (rule pairs p, p+256)
//  - -ed*Sxx term dropped (cancels in g = aw/s; exponent bounded ~27*log2e)

#define RULES 512
#define FEAT  128
#define RES   5
#define THREADS 512
#define WARPS (THREADS / 32)            // 16
#define RULES_PER_LANE (RULES / 32)     // 16
#define PAIR_ITERS (RULES_PER_LANE / 2) // 8
#define LOG2E 1.4426950408889634f

typedef unsigned long long u64;

__device__ __forceinline__ u64 pack2(float lo, float hi) {
    u64 r;
    asm("mov.b64 %0, {%1, %2};" : "=l"(r) : "f"(lo), "f"(hi));
    return r;
}
__device__ __forceinline__ void unpack2(float& lo, float& hi, u64 v) {
    asm("mov.b64 {%0, %1}, %2;" : "=f"(lo), "=f"(hi) : "l"(v));
}
__device__ __forceinline__ u64 fma2(u64 a, u64 b, u64 c) {
    u64 d;
    asm("fma.rn.f32x2 %0, %1, %2, %3;" : "=l"(d) : "l"(a), "l"(b), "l"(c));
    return d;
}
__device__ __forceinline__ u64 mul2(u64 a, u64 b) {
    u64 d;
    asm("mul.rn.f32x2 %0, %1, %2;" : "=l"(d) : "l"(a), "l"(b));
    return d;
}
__device__ __forceinline__ float ex2f(float x) {
    float y;
    asm("ex2.approx.ftz.f32 %0, %1;" : "=f"(y) : "f"(x));
    return y;
}

__global__ __launch_bounds__(THREADS)
void Model_68616397521448_kernel(const float* __restrict__ x,
                                 const float* __restrict__ a,
                                 const float* __restrict__ b,
                                 const float* __restrict__ r,
                                 const float* __restrict__ d,
                                 float* __restrict__ out,
                                 int batch)
{
    __shared__ float2 s_cc[RULES];               // {c0*log2e, c1*log2e}
    __shared__ float2 s_pb[RES][RULES / 2];      // pair p: {bel_c[p], bel_c[p+256]}

    const int tid  = threadIdx.x;
    const int warp = tid >> 5;
    const int lane = tid & 31;
    const int row  = warp * gridDim.x + blockIdx.x;   // interleaved rows

    // --- issue DRAM/L2 round trips first: x row + d scalar ---
    const int lrow = (row < batch) ? row : 0;
    const float4 xv = reinterpret_cast<const float4*>(x + (size_t)lrow * FEAT)[lane];
    const float ed = __expf(__ldg(d));

    // --- per-rule constants + beliefs softmax (1 rule/thread) ---
    if (tid < RULES) {
        const int j = tid;
        const float aj = a[j];
        // exponent in log2 domain: aw = 2^(c0 + c1*Sx)
        s_cc[j] = make_float2((r[j] - ed * 128.0f * aj * aj) * LOG2E,
                              (2.0f * ed * aj) * LOG2E);

        const float v0 = __expf(b[j * RES + 0]);
        const float v1 = __expf(b[j * RES + 1]);
        const float v2 = __expf(b[j * RES + 2]);
        const float v3 = __expf(b[j * RES + 3]);
        const float v4 = __expf(b[j * RES + 4]);
        const float inv = __fdividef(1.0f, (v0 + v1) + (v2 + v3) + v4);
        const int p    = j & 255;
        const int half = j >> 8;
        ((float*)&s_pb[0][p])[half] = v0 * inv;
        ((float*)&s_pb[1][p])[half] = v1 * inv;
        ((float*)&s_pb[2][p])[half] = v2 * inv;
        ((float*)&s_pb[3][p])[half] = v3 * inv;
        ((float*)&s_pb[4][p])[half] = v4 * inv;
    }

    // --- Sx reduce BEFORE the barrier: overlaps preamble/bar wait ---
    const float k5 = 0.2f;
    float Sx = ((xv.x + xv.y) + (xv.z + xv.w)) * k5;
#pragma unroll
    for (int off = 16; off; off >>= 1)
        Sx += __shfl_xor_sync(0xffffffffu, Sx, off);

    __syncthreads();

    if (row >= batch) return;

    // --- rule activations: aw_j = 2^(c0_j + c1_j*Sx) ---
    float aw[RULES_PER_LANE];
    float s = 0.0f;
#pragma unroll
    for (int k = 0; k < RULES_PER_LANE; k++) {
        const float2 cc = s_cc[(k << 5) + lane];
        aw[k] = ex2f(fmaf(cc.y, Sx, cc.x));
        s += aw[k];
    }
#pragma unroll
    for (int off = 16; off; off >>= 1)
        s += __shfl_xor_sync(0xffffffffu, s, off);
    const float invs = __fdividef(1.0f, s);
    const u64 invs2  = pack2(invs, invs);

    // --- division-free ER combine, rule pairs (p, p+256) in packed lanes ---
    const u64 one2  = 0x3f8000003f800000ull;  // {1,1}
    const u64 neg2  = 0xbf800000bf800000ull;  // {-1,-1}
    u64 n0 = one2, n1 = one2, n2 = one2, n3 = one2, n4 = one2, dd2 = one2;
#pragma unroll
    for (int t = 0; t < PAIR_ITERS; t++) {
        const int p = (t << 5) + lane;            // rules (p, p+256) = (aw[t], aw[t+8])
        const u64 gg = mul2(pack2(aw[t], aw[t + 8]), invs2);
        const u64 hh = fma2(gg, neg2, one2);      // {1-g, 1-g'}
        n0  = mul2(n0, fma2(gg, *(const u64*)&s_pb[0][p], hh));
        n1  = mul2(n1, fma2(gg, *(const u64*)&s_pb[1][p], hh));
        n2  = mul2(n2, fma2(gg, *(const u64*)&s_pb[2][p], hh));
        n3  = mul2(n3, fma2(gg, *(const u64*)&s_pb[3][p], hh));
        n4  = mul2(n4, fma2(gg, *(const u64*)&s_pb[4][p], hh));
        dd2 = mul2(dd2, hh);
    }
    // collapse packed halves -> scalars
    float lo, hi;
    unpack2(lo, hi, n0);  float c0v = lo * hi;
    unpack2(lo, hi, n1);  float c1v = lo * hi;
    unpack2(lo, hi, n2);  float c2v = lo * hi;
    unpack2(lo, hi, n3);  float c3v = lo * hi;
    unpack2(lo, hi, n4);  float c4v = lo * hi;
    unpack2(lo, hi, dd2); float ddv = lo * hi;

#pragma unroll
    for (int off = 16; off; off >>= 1) {
        c0v *= __shfl_xor_sync(0xffffffffu, c0v, off);
        c1v *= __shfl_xor_sync(0xffffffffu, c1v, off);
        c2v *= __shfl_xor_sync(0xffffffffu, c2v, off);
        c3v *= __shfl_xor_sync(0xffffffffu, c3v, off);
        c4v *= __shfl_xor_sync(0xffffffffu, c4v, off);
        ddv *= __shfl_xor_sync(0xffffffffu, ddv, off);
    }

    if (lane == 0) {
        // bc_c = n_c - dd (common denominator prod(s-aw) cancels in normalization)
        const float b0 = c0v - ddv;
        const float b1 = c1v - ddv;
        const float b2 = c2v - ddv;
        const float b3 = c3v - ddv;
        const float b4 = c4v - ddv;
        const float sb  = ((b0 + b1) + (b2 + b3)) + b4;
        // u = [-0.5, 0, 0.5, 1.0, 1.5]
        const float num = fmaf(-0.5f, b0, fmaf(0.5f, b2, fmaf(1.0f, b3, 1.5f * b4)));
        out[row] = __fdividef(num, sb);
    }
}

extern "C" void kernel_launch(void* const* d_in, const int* in_sizes, int n_in,
                              void* d_out, int out_size)
{
    const float* x = (const float*)d_in[0];
    const float* a = (const float*)d_in[1];
    const float* b = (const float*)d_in[2];
    const float* r = (const float*)d_in[3];
    const float* d = (const float*)d_in[4];
    float* out = (float*)d_out;

    const int batch = in_sizes[0] / FEAT;
    int grid = (batch + WARPS - 1) / WARPS;
    if (grid < 148) grid = 148;   // all SMs active (rows interleaved by warp)
    Model_68616397521448_kernel<<<grid, THREADS>>>(x, a, b, r, d, out, batch);
}

// round 8
// speedup vs baseline: 3.0721x; 3.0721x over previous
#include <cuda_runtime.h>

// Model_68616397521448 — fuzzy-rule evidential reasoning, round 8.
// Variance-controlled resubmit of the empirically best wall config (R5:
// 256 thr/block, grid=256, contiguous rows) + validated zero-cost cuts:
//  - exponent in log2 domain (ex2.approx, constants pre-scaled by log2e)
//  - Sx butterfly reduce hoisted above __syncthreads
//  - d prefetched via __ldg before the preamble
//  - division-free ER combine in packed f32x2 (rule pairs p, p+256)
//  - -ed*Sxx term dropped (cancels in g = aw/s)

#define RULES 512
#define FEAT  128
#define RES   5
#define THREADS 256
#define WARPS (THREADS / 32)            // 8
#define ROWS_PER_BLOCK WARPS            // 8
#define RULES_PER_LANE (RULES / 32)     // 16
#define PAIR_ITERS (RULES_PER_LANE / 2) // 8
#define LOG2E 1.4426950408889634f

typedef unsigned long long u64;

__device__ __forceinline__ u64 pack2(float lo, float hi) {
    u64 r;
    asm("mov.b64 %0, {%1, %2};" : "=l"(r) : "f"(lo), "f"(hi));
    return r;
}
__device__ __forceinline__ void unpack2(float& lo, float& hi, u64 v) {
    asm("mov.b64 {%0, %1}, %2;" : "=f"(lo), "=f"(hi) : "l"(v));
}
__device__ __forceinline__ u64 fma2(u64 a, u64 b, u64 c) {
    u64 d;
    asm("fma.rn.f32x2 %0, %1, %2, %3;" : "=l"(d) : "l"(a), "l"(b), "l"(c));
    return d;
}
__device__ __forceinline__ u64 mul2(u64 a, u64 b) {
    u64 d;
    asm("mul.rn.f32x2 %0, %1, %2;" : "=l"(d) : "l"(a), "l"(b));
    return d;
}
__device__ __forceinline__ float ex2f(float x) {
    float y;
    asm("ex2.approx.ftz.f32 %0, %1;" : "=f"(y) : "f"(x));
    return y;
}

__global__ __launch_bounds__(THREADS)
void Model_68616397521448_kernel(const float* __restrict__ x,
                                 const float* __restrict__ a,
                                 const float* __restrict__ b,
                                 const float* __restrict__ r,
                                 const float* __restrict__ d,
                                 float* __restrict__ out,
                                 int batch)
{
    __shared__ float2 s_cc[RULES];               // {c0*log2e, c1*log2e}
    __shared__ float2 s_pb[RES][RULES / 2];      // pair p: {bel_c[p], bel_c[p+256]}

    const int tid  = threadIdx.x;
    const int warp = tid >> 5;
    const int lane = tid & 31;
    const int row  = blockIdx.x * ROWS_PER_BLOCK + warp;

    // --- issue DRAM/L2 round trips first: x row + d scalar ---
    const int lrow = (row < batch) ? row : 0;
    const float4 xv = reinterpret_cast<const float4*>(x + (size_t)lrow * FEAT)[lane];
    const float ed = __expf(__ldg(d));

    // --- per-rule constants + beliefs softmax (2 rules/thread) ---
#pragma unroll
    for (int j = tid; j < RULES; j += THREADS) {
        const float aj = a[j];
        // exponent in log2 domain: aw = 2^(c0 + c1*Sx)
        s_cc[j] = make_float2((r[j] - ed * 128.0f * aj * aj) * LOG2E,
                              (2.0f * ed * aj) * LOG2E);

        const float v0 = __expf(b[j * RES + 0]);
        const float v1 = __expf(b[j * RES + 1]);
        const float v2 = __expf(b[j * RES + 2]);
        const float v3 = __expf(b[j * RES + 3]);
        const float v4 = __expf(b[j * RES + 4]);
        const float inv = __fdividef(1.0f, (v0 + v1) + (v2 + v3) + v4);
        const int p    = j & 255;
        const int half = j >> 8;
        ((float*)&s_pb[0][p])[half] = v0 * inv;
        ((float*)&s_pb[1][p])[half] = v1 * inv;
        ((float*)&s_pb[2][p])[half] = v2 * inv;
        ((float*)&s_pb[3][p])[half] = v3 * inv;
        ((float*)&s_pb[4][p])[half] = v4 * inv;
    }

    // --- Sx reduce BEFORE the barrier: overlaps preamble/bar wait ---
    const float k5 = 0.2f;
    float Sx = ((xv.x + xv.y) + (xv.z + xv.w)) * k5;
#pragma unroll
    for (int off = 16; off; off >>= 1)
        Sx += __shfl_xor_sync(0xffffffffu, Sx, off);

    __syncthreads();

    if (row >= batch) return;

    // --- rule activations: aw_j = 2^(c0_j + c1_j*Sx) ---
    float aw[RULES_PER_LANE];
    float s = 0.0f;
#pragma unroll
    for (int k = 0; k < RULES_PER_LANE; k++) {
        const float2 cc = s_cc[(k << 5) + lane];
        aw[k] = ex2f(fmaf(cc.y, Sx, cc.x));
        s += aw[k];
    }
#pragma unroll
    for (int off = 16; off; off >>= 1)
        s += __shfl_xor_sync(0xffffffffu, s, off);
    const float invs = __fdividef(1.0f, s);
    const u64 invs2  = pack2(invs, invs);

    // --- division-free ER combine, rule pairs (p, p+256) in packed lanes ---
    const u64 one2  = 0x3f8000003f800000ull;  // {1,1}
    const u64 neg2  = 0xbf800000bf800000ull;  // {-1,-1}
    u64 n0 = one2, n1 = one2, n2 = one2, n3 = one2, n4 = one2, dd2 = one2;
#pragma unroll
    for (int t = 0; t < PAIR_ITERS; t++) {
        const int p = (t << 5) + lane;            // rules (p, p+256) = (aw[t], aw[t+8])
        const u64 gg = mul2(pack2(aw[t], aw[t + 8]), invs2);
        const u64 hh = fma2(gg, neg2, one2);      // {1-g, 1-g'}
        n0  = mul2(n0, fma2(gg, *(const u64*)&s_pb[0][p], hh));
        n1  = mul2(n1, fma2(gg, *(const u64*)&s_pb[1][p], hh));
        n2  = mul2(n2, fma2(gg, *(const u64*)&s_pb[2][p], hh));
        n3  = mul2(n3, fma2(gg, *(const u64*)&s_pb[3][p], hh));
        n4  = mul2(n4, fma2(gg, *(const u64*)&s_pb[4][p], hh));
        dd2 = mul2(dd2, hh);
    }
    // collapse packed halves -> scalars
    float lo, hi;
    unpack2(lo, hi, n0);  float c0v = lo * hi;
    unpack2(lo, hi, n1);  float c1v = lo * hi;
    unpack2(lo, hi, n2);  float c2v = lo * hi;
    unpack2(lo, hi, n3);  float c3v = lo * hi;
    unpack2(lo, hi, n4);  float c4v = lo * hi;
    unpack2(lo, hi, dd2); float ddv = lo * hi;

    // final cross-lane product reduce: pack pairs to u64 shuffles
    u64 q01 = pack2(c0v, c1v);
    u64 q23 = pack2(c2v, c3v);
    u64 q4d = pack2(c4v, ddv);
#pragma unroll
    for (int off = 16; off; off >>= 1) {
        q01 = mul2(q01, __shfl_xor_sync(0xffffffffu, q01, off));
        q23 = mul2(q23, __shfl_xor_sync(0xffffffffu, q23, off));
        q4d = mul2(q4d, __shfl_xor_sync(0xffffffffu, q4d, off));
    }

    if (lane == 0) {
        float p0, p1, p2, p3, p4, dd;
        unpack2(p0, p1, q01);
        unpack2(p2, p3, q23);
        unpack2(p4, dd, q4d);
        // bc_c = n_c - dd (common denominator prod(s-aw) cancels in normalization)
        const float b0 = p0 - dd;
        const float b1 = p1 - dd;
        const float b2 = p2 - dd;
        const float b3 = p3 - dd;
        const float b4 = p4 - dd;
        const float sb  = ((b0 + b1) + (b2 + b3)) + b4;
        // u = [-0.5, 0, 0.5, 1.0, 1.5]
        const float num = fmaf(-0.5f, b0, fmaf(0.5f, b2, fmaf(1.0f, b3, 1.5f * b4)));
        out[row] = __fdividef(num, sb);
    }
}

extern "C" void kernel_launch(void* const* d_in, const int* in_sizes, int n_in,
                              void* d_out, int out_size)
{
    const float* x = (const float*)d_in[0];
    const float* a = (const float*)d_in[1];
    const float* b = (const float*)d_in[2];
    const float* r = (const float*)d_in[3];
    const float* d = (const float*)d_in[4];
    float* out = (float*)d_out;

    const int batch = in_sizes[0] / FEAT;
    const int grid = (batch + ROWS_PER_BLOCK - 1) / ROWS_PER_BLOCK;  // 256
    Model_68616397521448_kernel<<<grid, THREADS>>>(x, a, b, r, d, out, batch);
}